// round 14
// baseline (speedup 1.0000x reference)
#include <cuda_runtime.h>
#include <cuda_bf16.h>
#include <mma.h>
#include <math.h>

using namespace nvcuda;

#define BATCH 4096
#define NTAB  26
#define VOC   100000
#define EDIM  64
#define NPAIR 351
#define RDIM  448          // 64 + 351 padded to mult of 64 (cols 415..447 zeroed)
#define NB    296          // 2 CTAs x 148 SMs, guaranteed co-resident (128 thr, 37KB smem)

typedef __nv_bfloat16 bf16;
typedef long long ll;

// ---------------- scratch ----------------
__device__ bf16  g_xp  [BATCH * 64];
__device__ bf16  g_bw0p[512 * 64];
__device__ bf16  g_bw1p[256 * 512];
__device__ bf16  g_bw2p[64 * 256];
__device__ bf16  g_tw0p[512 * RDIM];
__device__ bf16  g_tw1p[256 * 512];
__device__ bf16  g_h0  [BATCH * 512];
__device__ bf16  g_h1  [BATCH * 256];
__device__ bf16  g_R   [BATCH * RDIM];
__device__ bf16  g_z0  [BATCH * 512];
__device__ bf16  g_z1  [BATCH * 256];

// ---------------- global barrier ----------------
__device__ unsigned g_cnt = 0;
__device__ volatile unsigned g_gen = 0;

__device__ __forceinline__ void grid_barrier()
{
    __syncthreads();
    if (threadIdx.x == 0) {
        __threadfence();
        unsigned gen = g_gen;
        if (atomicAdd(&g_cnt, 1) == NB - 1) {
            atomicExch(&g_cnt, 0);
            __threadfence();
            atomicAdd((unsigned*)&g_gen, 1);
        } else {
            while (g_gen == gen) __nanosleep(64);
        }
        __threadfence();
    }
    __syncthreads();
}

// ---------------- helpers ----------------
__device__ __forceinline__ unsigned su(const void* p) {
    return (unsigned)__cvta_generic_to_shared(p);
}
__device__ __forceinline__ void cpa16(unsigned d, const void* s) {
    asm volatile("cp.async.cg.shared.global [%0], [%1], 16;\n" :: "r"(d), "l"(s));
}

// ---------------- phase: pack fp32 -> bf16, K padded to mult of 64 ----------------
__device__ void phase_pack(const float* x, const float* bw0, const float* bw1,
                           const float* bw2, const float* tw0, const float* tw1)
{
    const ll nthr = (ll)NB * 128;
    for (ll gid = (ll)blockIdx.x * 128 + threadIdx.x; gid < 802816; gid += nthr) {
        const float* src; bf16* dst; int K, Kp; ll e;
        if (gid < 262144)       { src = x;   dst = g_xp;   K = 13;  Kp = 64;   e = gid; }
        else if (gid < 294912)  { src = bw0; dst = g_bw0p; K = 13;  Kp = 64;   e = gid - 262144; }
        else if (gid < 425984)  { src = bw1; dst = g_bw1p; K = 512; Kp = 512;  e = gid - 294912; }
        else if (gid < 442368)  { src = bw2; dst = g_bw2p; K = 256; Kp = 256;  e = gid - 425984; }
        else if (gid < 671744)  { src = tw0; dst = g_tw0p; K = 415; Kp = RDIM; e = gid - 442368; }
        else                    { src = tw1; dst = g_tw1p; K = 512; Kp = 512;  e = gid - 671744; }
        int n = (int)(e / Kp), k = (int)(e % Kp);
        float v = (k < K) ? src[(ll)n * K + k] : 0.f;
        dst[e] = __float2bfloat16_rn(v);
    }
}

// ---------------- phase: bf16 GEMM, tiles grid-strided (R11 inner config) ----------
// BM=BN=BK=64, 128 threads, 2-stage cp.async, relu+bias epilogue.
__device__ void gemm_phase(unsigned char* smraw, const bf16* __restrict__ A,
                           const bf16* __restrict__ W, const float* __restrict__ bias,
                           bf16* __restrict__ C, int Kp, int ldc, int ntn, int ntiles)
{
    constexpr int LDT = 72, LDCs = 36;
    bf16* sm0 = (bf16*)smraw;                    // 2 stages x 128 rows x 72
    const int tid  = threadIdx.x;
    const int wid  = tid >> 5;
    const int lane = tid & 31;
    const int warp_m = wid & 1;
    const int warp_n = wid >> 1;
    const int nk = Kp >> 6;

    for (int t = blockIdx.x; t < ntiles; t += NB) {
        const int bm = (t / ntn) * 64;
        const int bn = (t % ntn) * 64;
        __syncthreads();                         // smem reuse vs previous tile

        wmma::fragment<wmma::accumulator, 16, 16, 16, float> acc[2][2];
#pragma unroll
        for (int i = 0; i < 2; i++)
#pragma unroll
            for (int j = 0; j < 2; j++) wmma::fill_fragment(acc[i][j], 0.f);

        auto load_stage = [&](int st, int k0) {
            bf16* As = sm0 + st * (128 * LDT);
            bf16* Ws = As + 64 * LDT;
#pragma unroll
            for (int i = 0; i < 4; i++) {
                int id = tid + i * 128;
                int r = id >> 3, c8 = (id & 7) * 8;
                cpa16(su(As + r * LDT + c8), A + (ll)(bm + r) * Kp + k0 + c8);
            }
#pragma unroll
            for (int i = 0; i < 4; i++) {
                int id = tid + i * 128;
                int r = id >> 3, c8 = (id & 7) * 8;
                cpa16(su(Ws + r * LDT + c8), W + (ll)(bn + r) * Kp + k0 + c8);
            }
            asm volatile("cp.async.commit_group;\n");
        };

        load_stage(0, 0);
        for (int it = 0; it < nk; it++) {
            if (it + 1 < nk) {
                load_stage((it + 1) & 1, (it + 1) * 64);
                asm volatile("cp.async.wait_group 1;\n");
            } else {
                asm volatile("cp.async.wait_group 0;\n");
            }
            __syncthreads();

            const bf16* As = sm0 + (it & 1) * (128 * LDT);
            const bf16* Ws = As + 64 * LDT;
#pragma unroll
            for (int kk = 0; kk < 64; kk += 16) {
                wmma::fragment<wmma::matrix_a, 16, 16, 16, bf16, wmma::row_major> af[2];
                wmma::fragment<wmma::matrix_b, 16, 16, 16, bf16, wmma::col_major> bfg[2];
#pragma unroll
                for (int i = 0; i < 2; i++)
                    wmma::load_matrix_sync(af[i], As + (warp_m * 32 + i * 16) * LDT + kk, LDT);
#pragma unroll
                for (int j = 0; j < 2; j++)
                    wmma::load_matrix_sync(bfg[j], Ws + (warp_n * 32 + j * 16) * LDT + kk, LDT);
#pragma unroll
                for (int i = 0; i < 2; i++)
#pragma unroll
                    for (int j = 0; j < 2; j++)
                        wmma::mma_sync(acc[i][j], af[i], bfg[j], acc[i][j]);
            }
            __syncthreads();
        }

        float* Cw = (float*)smraw + wid * 32 * LDCs;
#pragma unroll
        for (int i = 0; i < 2; i++)
#pragma unroll
            for (int j = 0; j < 2; j++)
                wmma::store_matrix_sync(Cw + (i * 16) * LDCs + j * 16, acc[i][j], LDCs,
                                        wmma::mem_row_major);
        __syncwarp();

        const int n = bn + warp_n * 32 + lane;
        const float bv = bias[n];
#pragma unroll
        for (int r = 0; r < 32; r++) {
            int m = bm + warp_m * 32 + r;
            float v = fmaxf(Cw[r * LDCs + lane] + bv, 0.f);
            C[(ll)m * ldc + n] = __float2bfloat16_rn(v);
        }
    }
}

// ---------------- phase: fused embedding gather + interaction ----------------
__device__ void phase_interact(unsigned char* smraw, const void* __restrict__ lsi,
                               const float* __restrict__ emb)
{
    float (*Ts)[68] = (float(*)[68])smraw;                 // 27 x 68 x 4 = 7344 B
    int   (*sidx)[4] = (int(*)[4])(smraw + 7360);          // 416 B
    const int tid = threadIdx.x;

    const unsigned long long* q = (const unsigned long long*)lsi;
    const bool is64 = (q[0] < (unsigned long long)VOC) && (q[1] < (unsigned long long)VOC) &&
                      (q[2] < (unsigned long long)VOC) && (q[3] < (unsigned long long)VOC);

    for (int b = blockIdx.x; b < BATCH; b += NB) {
        __syncthreads();                                   // Ts reuse between rows
        if (tid < 64) Ts[0][tid] = __bfloat162float(g_R[(ll)b * RDIM + tid]);
        if (tid < NTAB * 4) {
            int t = tid >> 2, l = tid & 3;
            ll pos = ((ll)t * BATCH + b) * 4 + l;
            sidx[t][l] = is64 ? (int)((const ll*)lsi)[pos] : ((const int*)lsi)[pos];
        }
        __syncthreads();

        for (int u = tid; u < NTAB * 16; u += 128) {
            int t = u >> 4, q4 = u & 15;
            float4 s = make_float4(0.f, 0.f, 0.f, 0.f);
#pragma unroll
            for (int l = 0; l < 4; l++) {
                const float4 v = __ldg((const float4*)(emb +
                    ((ll)t * VOC + sidx[t][l]) * EDIM + q4 * 4));
                s.x += v.x; s.y += v.y; s.z += v.z; s.w += v.w;
            }
            *(float4*)&Ts[1 + t][q4 * 4] = s;
        }
        __syncthreads();

        for (int p = tid; p < NPAIR; p += 128) {
            int i = (int)((1.0f + sqrtf(1.0f + 8.0f * (float)p)) * 0.5f);
            while (i * (i - 1) / 2 > p) i--;
            while ((i + 1) * i / 2 <= p) i++;
            int j = p - i * (i - 1) / 2;

            const float4* ri = (const float4*)&Ts[i][0];
            const float4* rj = (const float4*)&Ts[j][0];
            float acc = 0.f;
#pragma unroll
            for (int k = 0; k < EDIM / 4; k++) {
                float4 a = ri[k], c = rj[k];
                acc += a.x * c.x + a.y * c.y + a.z * c.z + a.w * c.w;
            }
            g_R[(ll)b * RDIM + 64 + p] = __float2bfloat16_rn(acc);
        }
        if (tid < RDIM - 64 - NPAIR)
            g_R[(ll)b * RDIM + 64 + NPAIR + tid] = __float2bfloat16_rn(0.f);
    }
}

// ---------------- phase: final gemv + sigmoid ----------------
__device__ void phase_gemv(const float* __restrict__ w, const float* __restrict__ bias,
                           float* __restrict__ out)
{
    const int wglobal = blockIdx.x * 4 + (threadIdx.x >> 5);
    const int lane = threadIdx.x & 31;
    const float b0 = bias[0];
    for (int row = wglobal; row < BATCH; row += NB * 4) {
        float4 raw = *(const float4*)(g_z1 + (ll)row * 256 + lane * 8);
        const __nv_bfloat162* pr = (const __nv_bfloat162*)&raw;
        float s = 0.f;
#pragma unroll
        for (int i = 0; i < 4; i++) {
            float2 v = __bfloat1622float2(pr[i]);
            s += v.x * w[lane * 8 + 2 * i] + v.y * w[lane * 8 + 2 * i + 1];
        }
#pragma unroll
        for (int off = 16; off; off >>= 1) s += __shfl_xor_sync(0xffffffffu, s, off);
        if (lane == 0) out[row] = 1.f / (1.f + expf(-(s + b0)));
    }
}

// ---------------- the megakernel ----------------
__global__ void __launch_bounds__(128, 2)
dlrm_mega(const float* x, const void* lsi, const float* emb,
          const float* bw0, const float* bb0, const float* bw1, const float* bb1,
          const float* bw2, const float* bb2, const float* tw0, const float* tb0,
          const float* tw1, const float* tb1, const float* tw2, const float* tb2,
          float* out)
{
    __shared__ __align__(16) unsigned char smem[36864 + 384];

    phase_pack(x, bw0, bw1, bw2, tw0, tw1);
    grid_barrier();

    gemm_phase(smem, g_xp, g_bw0p, bb0, g_h0, 64,  512,  8, 512);
    grid_barrier();
    gemm_phase(smem, g_h0, g_bw1p, bb1, g_h1, 512, 256,  4, 256);
    grid_barrier();
    gemm_phase(smem, g_h1, g_bw2p, bb2, g_R,  256, RDIM, 1, 64);
    grid_barrier();

    phase_interact(smem, lsi, emb);
    grid_barrier();

    gemm_phase(smem, g_R,  g_tw0p, tb0, g_z0, RDIM, 512, 8, 512);
    grid_barrier();
    gemm_phase(smem, g_z0, g_tw1p, tb1, g_z1, 512,  256, 4, 256);
    grid_barrier();

    phase_gemv(tw2, tb2, out);
}

// ---------------- launch ----------------
extern "C" void kernel_launch(void* const* d_in, const int* in_sizes, int n_in,
                              void* d_out, int out_size)
{
    dlrm_mega<<<NB, 128>>>(
        (const float*)d_in[0], d_in[1], (const float*)d_in[2],
        (const float*)d_in[3], (const float*)d_in[4],
        (const float*)d_in[5], (const float*)d_in[6],
        (const float*)d_in[7], (const float*)d_in[8],
        (const float*)d_in[9], (const float*)d_in[10],
        (const float*)d_in[11], (const float*)d_in[12],
        (const float*)d_in[13], (const float*)d_in[14],
        (float*)d_out);
}

// round 15
// speedup vs baseline: 1.2345x; 1.2345x over previous
#include <cuda_runtime.h>
#include <cuda_bf16.h>
#include <mma.h>
#include <math.h>

using namespace nvcuda;

#define BATCH 4096
#define NTAB  26
#define VOC   100000
#define EDIM  64
#define NPAIR 351
#define RDIM  448          // 64 + 351 padded to mult of 64 (cols 415..447 zeroed)

typedef __nv_bfloat16 bf16;
typedef long long ll;

// ---------------- scratch ----------------
__device__ bf16  g_xp  [BATCH * 64];
__device__ bf16  g_bw0p[512 * 64];
__device__ bf16  g_bw1p[256 * 512];
__device__ bf16  g_bw2p[64 * 256];
__device__ bf16  g_tw0p[512 * RDIM];
__device__ bf16  g_tw1p[256 * 512];
__device__ bf16  g_h0  [BATCH * 512];
__device__ bf16  g_h1  [BATCH * 256];
__device__ bf16  g_R   [BATCH * RDIM];
__device__ bf16  g_z0  [BATCH * 512];
__device__ bf16  g_z1  [BATCH * 256];

// ---------------- helpers ----------------
__device__ __forceinline__ unsigned su(const void* p) {
    return (unsigned)__cvta_generic_to_shared(p);
}
__device__ __forceinline__ void cpa16(unsigned d, const void* s) {
    asm volatile("cp.async.cg.shared.global [%0], [%1], 16;\n" :: "r"(d), "l"(s));
}

// ---------------- pack: fp32 -> bf16, K padded to mult of 64 ----------------
__global__ void __launch_bounds__(256)
pack_all(const float* x, const float* bw0, const float* bw1, const float* bw2,
         const float* tw0, const float* tw1)
{
    ll gid = (ll)blockIdx.x * 256 + threadIdx.x;
    const float* src; bf16* dst; int K, Kp; ll e;
    if (gid < 262144)       { src = x;   dst = g_xp;   K = 13;  Kp = 64;   e = gid; }
    else if (gid < 294912)  { src = bw0; dst = g_bw0p; K = 13;  Kp = 64;   e = gid - 262144; }
    else if (gid < 425984)  { src = bw1; dst = g_bw1p; K = 512; Kp = 512;  e = gid - 294912; }
    else if (gid < 442368)  { src = bw2; dst = g_bw2p; K = 256; Kp = 256;  e = gid - 425984; }
    else if (gid < 671744)  { src = tw0; dst = g_tw0p; K = 415; Kp = RDIM; e = gid - 442368; }
    else if (gid < 802816)  { src = tw1; dst = g_tw1p; K = 512; Kp = 512;  e = gid - 671744; }
    else return;
    int n = (int)(e / Kp), k = (int)(e % Kp);
    float v = (k < K) ? src[(ll)n * K + k] : 0.f;
    dst[e] = __float2bfloat16_rn(v);
}

// ---------------- pipelined bf16 GEMM: BM=BN=64, BK=64, 128 thr (R11) ----------
template <int ACT>
__global__ void __launch_bounds__(128, 5)
gemm_bf16(const bf16* __restrict__ A, const bf16* __restrict__ W,
          const float* __restrict__ bias, bf16* __restrict__ C, int Kp, int ldc)
{
    constexpr int BM = 64, BN = 64, BK = 64, LDT = 72, LDCs = 36;
    __shared__ __align__(16) bf16 sm[2][(BM + BN) * LDT];   // 36.9 KB

    const int bm   = blockIdx.y * BM;
    const int bn   = blockIdx.x * BN;
    const int tid  = threadIdx.x;
    const int wid  = tid >> 5;
    const int lane = tid & 31;
    const int warp_m = wid & 1;
    const int warp_n = wid >> 1;
    const int nk = Kp / BK;

    wmma::fragment<wmma::accumulator, 16, 16, 16, float> acc[2][2];
#pragma unroll
    for (int i = 0; i < 2; i++)
#pragma unroll
        for (int j = 0; j < 2; j++) wmma::fill_fragment(acc[i][j], 0.f);

    auto load_stage = [&](int st, int k0) {
        bf16* As = sm[st];
        bf16* Ws = As + BM * LDT;
#pragma unroll
        for (int i = 0; i < 4; i++) {
            int id = tid + i * 128;
            int r = id >> 3, c8 = (id & 7) * 8;
            cpa16(su(As + r * LDT + c8), A + (ll)(bm + r) * Kp + k0 + c8);
        }
#pragma unroll
        for (int i = 0; i < 4; i++) {
            int id = tid + i * 128;
            int r = id >> 3, c8 = (id & 7) * 8;
            cpa16(su(Ws + r * LDT + c8), W + (ll)(bn + r) * Kp + k0 + c8);
        }
        asm volatile("cp.async.commit_group;\n");
    };

    load_stage(0, 0);

    for (int it = 0; it < nk; it++) {
        if (it + 1 < nk) {
            load_stage((it + 1) & 1, (it + 1) * BK);
            asm volatile("cp.async.wait_group 1;\n");
        } else {
            asm volatile("cp.async.wait_group 0;\n");
        }
        __syncthreads();

        const bf16* As = sm[it & 1];
        const bf16* Ws = As + BM * LDT;
#pragma unroll
        for (int kk = 0; kk < BK; kk += 16) {
            wmma::fragment<wmma::matrix_a, 16, 16, 16, bf16, wmma::row_major> af[2];
            wmma::fragment<wmma::matrix_b, 16, 16, 16, bf16, wmma::col_major> bfg[2];
#pragma unroll
            for (int i = 0; i < 2; i++)
                wmma::load_matrix_sync(af[i], As + (warp_m * 32 + i * 16) * LDT + kk, LDT);
#pragma unroll
            for (int j = 0; j < 2; j++)
                wmma::load_matrix_sync(bfg[j], Ws + (warp_n * 32 + j * 16) * LDT + kk, LDT);
#pragma unroll
            for (int i = 0; i < 2; i++)
#pragma unroll
                for (int j = 0; j < 2; j++)
                    wmma::mma_sync(acc[i][j], af[i], bfg[j], acc[i][j]);
        }
        __syncthreads();
    }

    float* Cw = (float*)sm + wid * 32 * LDCs;
#pragma unroll
    for (int i = 0; i < 2; i++)
#pragma unroll
        for (int j = 0; j < 2; j++)
            wmma::store_matrix_sync(Cw + (i * 16) * LDCs + j * 16, acc[i][j], LDCs,
                                    wmma::mem_row_major);
    __syncwarp();

    const int n = bn + warp_n * 32 + lane;
    const float bv = bias[n];
#pragma unroll
    for (int r = 0; r < 32; r++) {
        int m = bm + warp_m * 32 + r;
        float v = Cw[r * LDCs + lane] + bv;
        if (ACT == 1) v = fmaxf(v, 0.f);
        C[(ll)m * ldc + n] = __float2bfloat16_rn(v);
    }
}

// ---------------- fused L3 + embedding gather + interaction ----------------
// One 128-thr block per batch row:
//   h = relu(h1[b]·bw2^T + bb2)   (64x256 matvec, weights L1-resident)
//   T[1..26] = embedding gather-sums
//   R[b] = [h | tril dots | 0-pad]
__global__ void __launch_bounds__(128)
gather_interact(const bf16* __restrict__ h1, const bf16* __restrict__ w2,
                const float* __restrict__ bb2,
                const void* __restrict__ lsi, const float* __restrict__ emb,
                bf16* __restrict__ R)
{
    __shared__ float Ts[27][68];
    __shared__ int   sidx[26][4];
    __shared__ float h1s[256];
    __shared__ float part[128];

    const int b   = blockIdx.x;
    const int tid = threadIdx.x;

    const unsigned long long* q = (const unsigned long long*)lsi;
    const bool is64 = (q[0] < (unsigned long long)VOC) && (q[1] < (unsigned long long)VOC) &&
                      (q[2] < (unsigned long long)VOC) && (q[3] < (unsigned long long)VOC);

    // stage h1 row (256 bf16) into smem as fp32
    if (tid < 32) {
        float4 raw = ((const float4*)(h1 + (ll)b * 256))[tid];
        const __nv_bfloat162* pr = (const __nv_bfloat162*)&raw;
#pragma unroll
        for (int i = 0; i < 4; i++) {
            float2 v = __bfloat1622float2(pr[i]);
            h1s[tid * 8 + 2 * i]     = v.x;
            h1s[tid * 8 + 2 * i + 1] = v.y;
        }
    }
    if (tid < NTAB * 4) {
        int t = tid >> 2, l = tid & 3;
        ll pos = ((ll)t * BATCH + b) * 4 + l;
        sidx[t][l] = is64 ? (int)((const ll*)lsi)[pos] : ((const int*)lsi)[pos];
    }
    __syncthreads();

    // L3 matvec: thread = (col = tid&63, half = tid>>6); 128 MACs each
    {
        const int col = tid & 63, half = tid >> 6;
        const float4* wp = (const float4*)(w2 + (ll)col * 256 + half * 128);
        const float*  hp = h1s + half * 128;
        float acc = 0.f;
#pragma unroll
        for (int i = 0; i < 16; i++) {
            float4 raw = __ldg(&wp[i]);
            const __nv_bfloat162* pr = (const __nv_bfloat162*)&raw;
#pragma unroll
            for (int j = 0; j < 4; j++) {
                float2 wv = __bfloat1622float2(pr[j]);
                acc += wv.x * hp[i * 8 + 2 * j] + wv.y * hp[i * 8 + 2 * j + 1];
            }
        }
        part[tid] = acc;
    }
    __syncthreads();
    if (tid < 64) {
        float h = fmaxf(part[tid] + part[tid + 64] + bb2[tid], 0.f);
        Ts[0][tid] = h;
        R[(ll)b * RDIM + tid] = __float2bfloat16_rn(h);
    }

    // embedding gather-sums into Ts[1..26]
    for (int u = tid; u < NTAB * 16; u += 128) {
        int t = u >> 4, q4 = u & 15;
        float4 s = make_float4(0.f, 0.f, 0.f, 0.f);
#pragma unroll
        for (int l = 0; l < 4; l++) {
            const float4 v = __ldg((const float4*)(emb +
                ((ll)t * VOC + sidx[t][l]) * EDIM + q4 * 4));
            s.x += v.x; s.y += v.y; s.z += v.z; s.w += v.w;
        }
        *(float4*)&Ts[1 + t][q4 * 4] = s;
    }
    __syncthreads();

    for (int p = tid; p < NPAIR; p += 128) {
        int i = (int)((1.0f + sqrtf(1.0f + 8.0f * (float)p)) * 0.5f);
        while (i * (i - 1) / 2 > p) i--;
        while ((i + 1) * i / 2 <= p) i++;
        int j = p - i * (i - 1) / 2;

        const float4* ri = (const float4*)&Ts[i][0];
        const float4* rj = (const float4*)&Ts[j][0];
        float acc = 0.f;
#pragma unroll
        for (int k = 0; k < EDIM / 4; k++) {
            float4 a = ri[k], c = rj[k];
            acc += a.x * c.x + a.y * c.y + a.z * c.z + a.w * c.w;
        }
        R[(ll)b * RDIM + 64 + p] = __float2bfloat16_rn(acc);
    }
    if (tid < RDIM - 64 - NPAIR)
        R[(ll)b * RDIM + 64 + NPAIR + tid] = __float2bfloat16_rn(0.f);
}

// ---------------- final layer ----------------
__global__ void __launch_bounds__(256)
gemv_sigmoid(const bf16* __restrict__ A, const float* __restrict__ w,
             const float* __restrict__ bias, float* __restrict__ out)
{
    const int row  = blockIdx.x * 8 + (threadIdx.x >> 5);
    const int lane = threadIdx.x & 31;
    float4 raw = *(const float4*)(A + (ll)row * 256 + lane * 8);
    const __nv_bfloat162* pr = (const __nv_bfloat162*)&raw;
    float s = 0.f;
#pragma unroll
    for (int i = 0; i < 4; i++) {
        float2 v = __bfloat1622float2(pr[i]);
        s += v.x * w[lane * 8 + 2 * i] + v.y * w[lane * 8 + 2 * i + 1];
    }
#pragma unroll
    for (int off = 16; off; off >>= 1) s += __shfl_xor_sync(0xffffffffu, s, off);
    if (lane == 0) out[row] = 1.f / (1.f + expf(-(s + bias[0])));
}

// ---------------- launch ----------------
extern "C" void kernel_launch(void* const* d_in, const int* in_sizes, int n_in,
                              void* d_out, int out_size)
{
    const float* x    = (const float*)d_in[0];
    const void*  lsi  = d_in[1];
    const float* emb  = (const float*)d_in[2];
    const float* bw0  = (const float*)d_in[3];
    const float* bb0  = (const float*)d_in[4];
    const float* bw1  = (const float*)d_in[5];
    const float* bb1  = (const float*)d_in[6];
    const float* bw2  = (const float*)d_in[7];
    const float* bb2  = (const float*)d_in[8];
    const float* tw0  = (const float*)d_in[9];
    const float* tb0  = (const float*)d_in[10];
    const float* tw1  = (const float*)d_in[11];
    const float* tb1  = (const float*)d_in[12];
    const float* tw2  = (const float*)d_in[13];
    const float* tb2  = (const float*)d_in[14];
    float* out = (float*)d_out;

    bf16 *xp, *bw0p, *bw1p, *bw2p, *tw0p, *tw1p, *h0, *h1, *R, *z0, *z1;
    cudaGetSymbolAddress((void**)&xp,   g_xp);
    cudaGetSymbolAddress((void**)&bw0p, g_bw0p);
    cudaGetSymbolAddress((void**)&bw1p, g_bw1p);
    cudaGetSymbolAddress((void**)&bw2p, g_bw2p);
    cudaGetSymbolAddress((void**)&tw0p, g_tw0p);
    cudaGetSymbolAddress((void**)&tw1p, g_tw1p);
    cudaGetSymbolAddress((void**)&h0,   g_h0);
    cudaGetSymbolAddress((void**)&h1,   g_h1);
    cudaGetSymbolAddress((void**)&R,    g_R);
    cudaGetSymbolAddress((void**)&z0,   g_z0);
    cudaGetSymbolAddress((void**)&z1,   g_z1);

    pack_all<<<3136, 256>>>(x, bw0, bw1, bw2, tw0, tw1);

    // bottom MLP layers 1-2 (L3 fused into gather_interact)
    gemm_bf16<1><<<dim3(8, 64), 128>>>(xp, bw0p, bb0, h0, 64,  512);
    gemm_bf16<1><<<dim3(4, 64), 128>>>(h0, bw1p, bb1, h1, 512, 256);

    // fused L3 + gather + interaction -> R[:, 0:415] (+ zero pad)
    gather_interact<<<BATCH, 128>>>(h1, bw2p, bb2, lsi, emb, R);

    // top MLP
    gemm_bf16<1><<<dim3(8, 64), 128>>>(R,  tw0p, tb0, z0, RDIM, 512);
    gemm_bf16<1><<<dim3(4, 64), 128>>>(z0, tw1p, tb1, z1, 512,  256);
    gemv_sigmoid<<<BATCH / 8, 256>>>(z1, tw2, tb2, out);
}

// round 16
// speedup vs baseline: 1.8679x; 1.5130x over previous
#include <cuda_runtime.h>
#include <cuda_bf16.h>
#include <mma.h>
#include <math.h>

using namespace nvcuda;

#define BATCH 4096
#define NTAB  26
#define VOC   100000
#define EDIM  64
#define NPAIR 351
#define RDIM  448          // 64 + 351 padded to mult of 64 (cols 415..447 zeroed)

typedef __nv_bfloat16 bf16;
typedef long long ll;

// ---------------- scratch ----------------
__device__ bf16  g_xp  [BATCH * 64];
__device__ bf16  g_bw0p[512 * 64];
__device__ bf16  g_bw1p[256 * 512];
__device__ bf16  g_bw2p[64 * 256];
__device__ bf16  g_tw0p[512 * RDIM];
__device__ bf16  g_tw1p[256 * 512];
__device__ bf16  g_h0  [BATCH * 512];
__device__ bf16  g_h1  [BATCH * 256];
__device__ bf16  g_R   [BATCH * RDIM];
__device__ bf16  g_z0  [BATCH * 512];
__device__ bf16  g_z1  [BATCH * 256];

// ---------------- helpers ----------------
__device__ __forceinline__ unsigned su(const void* p) {
    return (unsigned)__cvta_generic_to_shared(p);
}
__device__ __forceinline__ void cpa16(unsigned d, const void* s) {
    asm volatile("cp.async.cg.shared.global [%0], [%1], 16;\n" :: "r"(d), "l"(s));
}

// ---------------- pack: fp32 -> bf16, K padded to mult of 64 ----------------
__global__ void __launch_bounds__(256)
pack_all(const float* x, const float* bw0, const float* bw1, const float* bw2,
         const float* tw0, const float* tw1)
{
    ll gid = (ll)blockIdx.x * 256 + threadIdx.x;
    const float* src; bf16* dst; int K, Kp; ll e;
    if (gid < 262144)       { src = x;   dst = g_xp;   K = 13;  Kp = 64;   e = gid; }
    else if (gid < 294912)  { src = bw0; dst = g_bw0p; K = 13;  Kp = 64;   e = gid - 262144; }
    else if (gid < 425984)  { src = bw1; dst = g_bw1p; K = 512; Kp = 512;  e = gid - 294912; }
    else if (gid < 442368)  { src = bw2; dst = g_bw2p; K = 256; Kp = 256;  e = gid - 425984; }
    else if (gid < 671744)  { src = tw0; dst = g_tw0p; K = 415; Kp = RDIM; e = gid - 442368; }
    else if (gid < 802816)  { src = tw1; dst = g_tw1p; K = 512; Kp = 512;  e = gid - 671744; }
    else return;
    int n = (int)(e / Kp), k = (int)(e % Kp);
    float v = (k < K) ? src[(ll)n * K + k] : 0.f;
    dst[e] = __float2bfloat16_rn(v);
}

// ---------------- pipelined bf16 GEMM: BM=BN=64, BK=64, 128 thr (R11) ----------
template <int ACT>
__global__ void __launch_bounds__(128, 5)
gemm_bf16(const bf16* __restrict__ A, const bf16* __restrict__ W,
          const float* __restrict__ bias, bf16* __restrict__ C, int Kp, int ldc)
{
    constexpr int BM = 64, BN = 64, BK = 64, LDT = 72, LDCs = 36;
    __shared__ __align__(16) bf16 sm[2][(BM + BN) * LDT];   // 36.9 KB

    const int bm   = blockIdx.y * BM;
    const int bn   = blockIdx.x * BN;
    const int tid  = threadIdx.x;
    const int wid  = tid >> 5;
    const int lane = tid & 31;
    const int warp_m = wid & 1;
    const int warp_n = wid >> 1;
    const int nk = Kp / BK;

    wmma::fragment<wmma::accumulator, 16, 16, 16, float> acc[2][2];
#pragma unroll
    for (int i = 0; i < 2; i++)
#pragma unroll
        for (int j = 0; j < 2; j++) wmma::fill_fragment(acc[i][j], 0.f);

    auto load_stage = [&](int st, int k0) {
        bf16* As = sm[st];
        bf16* Ws = As + BM * LDT;
#pragma unroll
        for (int i = 0; i < 4; i++) {
            int id = tid + i * 128;
            int r = id >> 3, c8 = (id & 7) * 8;
            cpa16(su(As + r * LDT + c8), A + (ll)(bm + r) * Kp + k0 + c8);
        }
#pragma unroll
        for (int i = 0; i < 4; i++) {
            int id = tid + i * 128;
            int r = id >> 3, c8 = (id & 7) * 8;
            cpa16(su(Ws + r * LDT + c8), W + (ll)(bn + r) * Kp + k0 + c8);
        }
        asm volatile("cp.async.commit_group;\n");
    };

    load_stage(0, 0);

    for (int it = 0; it < nk; it++) {
        if (it + 1 < nk) {
            load_stage((it + 1) & 1, (it + 1) * BK);
            asm volatile("cp.async.wait_group 1;\n");
        } else {
            asm volatile("cp.async.wait_group 0;\n");
        }
        __syncthreads();

        const bf16* As = sm[it & 1];
        const bf16* Ws = As + BM * LDT;
#pragma unroll
        for (int kk = 0; kk < BK; kk += 16) {
            wmma::fragment<wmma::matrix_a, 16, 16, 16, bf16, wmma::row_major> af[2];
            wmma::fragment<wmma::matrix_b, 16, 16, 16, bf16, wmma::col_major> bfg[2];
#pragma unroll
            for (int i = 0; i < 2; i++)
                wmma::load_matrix_sync(af[i], As + (warp_m * 32 + i * 16) * LDT + kk, LDT);
#pragma unroll
            for (int j = 0; j < 2; j++)
                wmma::load_matrix_sync(bfg[j], Ws + (warp_n * 32 + j * 16) * LDT + kk, LDT);
#pragma unroll
            for (int i = 0; i < 2; i++)
#pragma unroll
                for (int j = 0; j < 2; j++)
                    wmma::mma_sync(acc[i][j], af[i], bfg[j], acc[i][j]);
        }
        __syncthreads();
    }

    float* Cw = (float*)sm + wid * 32 * LDCs;
#pragma unroll
    for (int i = 0; i < 2; i++)
#pragma unroll
        for (int j = 0; j < 2; j++)
            wmma::store_matrix_sync(Cw + (i * 16) * LDCs + j * 16, acc[i][j], LDCs,
                                    wmma::mem_row_major);
    __syncwarp();

    const int n = bn + warp_n * 32 + lane;
    const float bv = bias[n];
#pragma unroll
    for (int r = 0; r < 32; r++) {
        int m = bm + warp_m * 32 + r;
        float v = Cw[r * LDCs + lane] + bv;
        if (ACT == 1) v = fmaxf(v, 0.f);
        C[(ll)m * ldc + n] = __float2bfloat16_rn(v);
    }
}

// ---------------- fused embedding gather + tensor-core interaction ----------------
// One 128-thr block per batch row. Gather-sums stored as bf16 T[32][72] (rows
// 27..31 zero); Z = T·T^T via 4 warps x one 16x16 wmma tile (k=64); tril
// extraction from fp32 Cs.
__global__ void __launch_bounds__(128)
gather_interact(const void* __restrict__ lsi, const float* __restrict__ emb,
                bf16* __restrict__ R)
{
    __shared__ __align__(16) bf16  Tb[32 * 72];     // 4.6 KB
    __shared__ __align__(16) float Cs[32 * 36];     // 4.6 KB
    __shared__ int sidx[26][4];

    const int b   = blockIdx.x;
    const int tid = threadIdx.x;

    const unsigned long long* q = (const unsigned long long*)lsi;
    const bool is64 = (q[0] < (unsigned long long)VOC) && (q[1] < (unsigned long long)VOC) &&
                      (q[2] < (unsigned long long)VOC) && (q[3] < (unsigned long long)VOC);

    // row 0 = h (bf16 copy from R[:,0:64]); zero rows 27..31 (cols 0..63)
    if (tid < 64) Tb[tid] = R[(ll)b * RDIM + tid];
    for (int idx = tid; idx < 5 * 64; idx += 128)
        Tb[(27 + (idx >> 6)) * 72 + (idx & 63)] = __float2bfloat16_rn(0.f);
    if (tid < NTAB * 4) {
        int t = tid >> 2, l = tid & 3;
        ll pos = ((ll)t * BATCH + b) * 4 + l;
        sidx[t][l] = is64 ? (int)((const ll*)lsi)[pos] : ((const int*)lsi)[pos];
    }
    __syncthreads();

    // gather-sum: 416 units = (table, 16B quarter); explicit pairs for MLP=8
    auto fetch = [&](int u, float4 v[4]) {
        int t = u >> 4, q4 = u & 15;
#pragma unroll
        for (int l = 0; l < 4; l++)
            v[l] = __ldg((const float4*)(emb +
                ((ll)t * VOC + sidx[t][l]) * EDIM + q4 * 4));
    };
    auto reduce_store = [&](int u, float4 v[4]) {
        float sx = v[0].x + v[1].x + v[2].x + v[3].x;
        float sy = v[0].y + v[1].y + v[2].y + v[3].y;
        float sz = v[0].z + v[1].z + v[2].z + v[3].z;
        float sw = v[0].w + v[1].w + v[2].w + v[3].w;
        __nv_bfloat162 p0 = __floats2bfloat162_rn(sx, sy);
        __nv_bfloat162 p1 = __floats2bfloat162_rn(sz, sw);
        uint2 pk;
        pk.x = *(unsigned*)&p0;
        pk.y = *(unsigned*)&p1;
        int t = u >> 4, q4 = u & 15;
        *(uint2*)(Tb + (1 + t) * 72 + q4 * 4) = pk;
    };

    {
        float4 v0[4], v1[4];
        fetch(tid, v0);
        fetch(tid + 128, v1);
        reduce_store(tid, v0);
        reduce_store(tid + 128, v1);
        fetch(tid + 256, v0);
        if (tid < 32) fetch(tid + 384, v1);
        reduce_store(tid + 256, v0);
        if (tid < 32) reduce_store(tid + 384, v1);
    }
    __syncthreads();

    // Z = T·T^T (32x32x64): warp w computes tile (w&1, w>>1)
    {
        const int wid = tid >> 5;
        const int wm = wid & 1, wn = wid >> 1;
        wmma::fragment<wmma::accumulator, 16, 16, 16, float> acc;
        wmma::fill_fragment(acc, 0.f);
#pragma unroll
        for (int kk = 0; kk < 64; kk += 16) {
            wmma::fragment<wmma::matrix_a, 16, 16, 16, bf16, wmma::row_major> af;
            wmma::fragment<wmma::matrix_b, 16, 16, 16, bf16, wmma::col_major> bfg;
            wmma::load_matrix_sync(af,  Tb + (wm * 16) * 72 + kk, 72);
            wmma::load_matrix_sync(bfg, Tb + (wn * 16) * 72 + kk, 72);
            wmma::mma_sync(acc, af, bfg, acc);
        }
        wmma::store_matrix_sync(Cs + (wm * 16) * 36 + wn * 16, acc, 36,
                                wmma::mem_row_major);
    }
    __syncthreads();

    // tril extraction (row-major tril_indices order)
    for (int p = tid; p < NPAIR; p += 128) {
        int i = (int)((1.0f + sqrtf(1.0f + 8.0f * (float)p)) * 0.5f);
        while (i * (i - 1) / 2 > p) i--;
        while ((i + 1) * i / 2 <= p) i++;
        int j = p - i * (i - 1) / 2;
        R[(ll)b * RDIM + 64 + p] = __float2bfloat16_rn(Cs[i * 36 + j]);
    }
    if (tid < RDIM - 64 - NPAIR)
        R[(ll)b * RDIM + 64 + NPAIR + tid] = __float2bfloat16_rn(0.f);
}

// ---------------- final layer ----------------
__global__ void __launch_bounds__(256)
gemv_sigmoid(const bf16* __restrict__ A, const float* __restrict__ w,
             const float* __restrict__ bias, float* __restrict__ out)
{
    const int row  = blockIdx.x * 8 + (threadIdx.x >> 5);
    const int lane = threadIdx.x & 31;
    float4 raw = *(const float4*)(A + (ll)row * 256 + lane * 8);
    const __nv_bfloat162* pr = (const __nv_bfloat162*)&raw;
    float s = 0.f;
#pragma unroll
    for (int i = 0; i < 4; i++) {
        float2 v = __bfloat1622float2(pr[i]);
        s += v.x * w[lane * 8 + 2 * i] + v.y * w[lane * 8 + 2 * i + 1];
    }
#pragma unroll
    for (int off = 16; off; off >>= 1) s += __shfl_xor_sync(0xffffffffu, s, off);
    if (lane == 0) out[row] = 1.f / (1.f + expf(-(s + bias[0])));
}

// ---------------- launch ----------------
extern "C" void kernel_launch(void* const* d_in, const int* in_sizes, int n_in,
                              void* d_out, int out_size)
{
    const float* x    = (const float*)d_in[0];
    const void*  lsi  = d_in[1];
    const float* emb  = (const float*)d_in[2];
    const float* bw0  = (const float*)d_in[3];
    const float* bb0  = (const float*)d_in[4];
    const float* bw1  = (const float*)d_in[5];
    const float* bb1  = (const float*)d_in[6];
    const float* bw2  = (const float*)d_in[7];
    const float* bb2  = (const float*)d_in[8];
    const float* tw0  = (const float*)d_in[9];
    const float* tb0  = (const float*)d_in[10];
    const float* tw1  = (const float*)d_in[11];
    const float* tb1  = (const float*)d_in[12];
    const float* tw2  = (const float*)d_in[13];
    const float* tb2  = (const float*)d_in[14];
    float* out = (float*)d_out;

    bf16 *xp, *bw0p, *bw1p, *bw2p, *tw0p, *tw1p, *h0, *h1, *R, *z0, *z1;
    cudaGetSymbolAddress((void**)&xp,   g_xp);
    cudaGetSymbolAddress((void**)&bw0p, g_bw0p);
    cudaGetSymbolAddress((void**)&bw1p, g_bw1p);
    cudaGetSymbolAddress((void**)&bw2p, g_bw2p);
    cudaGetSymbolAddress((void**)&tw0p, g_tw0p);
    cudaGetSymbolAddress((void**)&tw1p, g_tw1p);
    cudaGetSymbolAddress((void**)&h0,   g_h0);
    cudaGetSymbolAddress((void**)&h1,   g_h1);
    cudaGetSymbolAddress((void**)&R,    g_R);
    cudaGetSymbolAddress((void**)&z0,   g_z0);
    cudaGetSymbolAddress((void**)&z1,   g_z1);

    pack_all<<<3136, 256>>>(x, bw0, bw1, bw2, tw0, tw1);

    // bottom MLP; layer 3 writes into R[:, 0:64]
    gemm_bf16<1><<<dim3(8, 64), 128>>>(xp, bw0p, bb0, h0, 64,  512);
    gemm_bf16<1><<<dim3(4, 64), 128>>>(h0, bw1p, bb1, h1, 512, 256);
    gemm_bf16<1><<<dim3(1, 64), 128>>>(h1, bw2p, bb2, R,  256, RDIM);

    // fused gather + tensor-core interaction -> R[:, 64:415] (+ zero pad)
    gather_interact<<<BATCH, 128>>>(lsi, emb, R);

    // top MLP
    gemm_bf16<1><<<dim3(8, 64), 128>>>(R,  tw0p, tb0, z0, RDIM, 512);
    gemm_bf16<1><<<dim3(4, 64), 128>>>(z0, tw1p, tb1, z1, 512,  256);
    gemv_sigmoid<<<BATCH / 8, 256>>>(z1, tw2, tb2, out);
}